// round 2
// baseline (speedup 1.0000x reference)
#include <cuda_runtime.h>
#include <stdint.h>
#include <math.h>

#define N_NODES 100000
#define N_PAD   100096        // multiple of 128 for tile padding
#define DIM     64
#define HID     256
#define BN_EPS  1e-5f

// ---------------- scratch (static device globals; no allocation) ----------------
__device__ int   g_deg[N_PAD];
__device__ int   g_rowstart[N_PAD];
__device__ int   g_cursor[N_PAD];
__device__ int   g_csr[1600000];
__device__ int   g_total;
__device__ float g_x [(size_t)N_PAD * DIM];   // combined agg/deg + h
__device__ float g_colsum[DIM];
__device__ float g_colsq [DIM];
__device__ __align__(16) float g_scale[DIM];
__device__ __align__(16) float g_shift[DIM];

// ---------------- packed f32x2 helpers (sm_10x FFMA2) ----------------
__device__ __forceinline__ void fma2(unsigned long long &d, unsigned long long a,
                                     unsigned long long b) {
    asm("fma.rn.f32x2 %0, %1, %2, %0;" : "+l"(d) : "l"(a), "l"(b));
}
__device__ __forceinline__ unsigned long long pack2(float lo, float hi) {
    unsigned long long r;
    asm("mov.b64 %0, {%1,%2};" : "=l"(r) : "f"(lo), "f"(hi));
    return r;
}
__device__ __forceinline__ void unpack2(unsigned long long v, float &lo, float &hi) {
    asm("mov.b64 {%0,%1}, %2;" : "=f"(lo), "=f"(hi) : "l"(v));
}

// ---------------- CSR build ----------------
__global__ void k_zero() {
    int i = blockIdx.x * blockDim.x + threadIdx.x;
    if (i < N_PAD) g_deg[i] = 0;
    if (i < DIM) { g_colsum[i] = 0.f; g_colsq[i] = 0.f; }
    if (i == 0) g_total = 0;
    const int padN = N_PAD - N_NODES;           // 96
    if (i < padN * DIM) g_x[(size_t)N_NODES * DIM + i] = 0.f;
}

__global__ void k_hist(const int* __restrict__ dst, int E) {
    int i = blockIdx.x * blockDim.x + threadIdx.x;
    if (i < E) atomicAdd(&g_deg[dst[i]], 1);
}

// one-kernel exclusive scan: block-local Hillis-Steele + atomic base allocation.
__global__ void k_scan() {
    __shared__ int s[256];
    __shared__ int sbase;
    int t = threadIdx.x;
    int i = blockIdx.x * 256 + t;
    int d = (i < N_NODES) ? g_deg[i] : 0;
    s[t] = d;
    __syncthreads();
    for (int off = 1; off < 256; off <<= 1) {
        int v = (t >= off) ? s[t - off] : 0;
        __syncthreads();
        s[t] += v;
        __syncthreads();
    }
    if (t == 255) sbase = atomicAdd(&g_total, s[255]);
    __syncthreads();
    if (i < N_NODES) {
        int start = sbase + s[t] - d;   // exclusive
        g_rowstart[i] = start;
        g_cursor[i]   = start;
    }
}

__global__ void k_fill(const int* __restrict__ src, const int* __restrict__ dst, int E) {
    int i = blockIdx.x * blockDim.x + threadIdx.x;
    if (i < E) {
        int d = dst[i];
        int pos = atomicAdd(&g_cursor[d], 1);
        g_csr[pos] = src[i];
    }
}

// ---------------- aggregation ----------------
// warp-per-node gather: x[n] = segsum(h[src])/max(deg,1) + h[n]
// batch-load 32 indices coalesced, shuffle-broadcast, unroll x4 for MLP.
__global__ void k_agg(const float* __restrict__ h) {
    int node = (blockIdx.x * blockDim.x + threadIdx.x) >> 5;
    int lane = threadIdx.x & 31;
    if (node >= N_NODES) return;
    int start = g_rowstart[node];
    int deg   = g_deg[node];
    float a0 = 0.f, a1 = 0.f, b0 = 0.f, b1 = 0.f;
    int j = 0;
    while (j < deg) {
        int cnt = min(32, deg - j);
        int idx = 0;
        if (lane < cnt) idx = __ldg(&g_csr[start + j + lane]);
        int jj = 0;
        for (; jj + 4 <= cnt; jj += 4) {
            int s0 = __shfl_sync(0xffffffffu, idx, jj);
            int s1 = __shfl_sync(0xffffffffu, idx, jj + 1);
            int s2 = __shfl_sync(0xffffffffu, idx, jj + 2);
            int s3 = __shfl_sync(0xffffffffu, idx, jj + 3);
            float v0 = __ldg(&h[(size_t)s0 * DIM + lane]);
            float w0 = __ldg(&h[(size_t)s0 * DIM + lane + 32]);
            float v1 = __ldg(&h[(size_t)s1 * DIM + lane]);
            float w1 = __ldg(&h[(size_t)s1 * DIM + lane + 32]);
            float v2 = __ldg(&h[(size_t)s2 * DIM + lane]);
            float w2 = __ldg(&h[(size_t)s2 * DIM + lane + 32]);
            float v3 = __ldg(&h[(size_t)s3 * DIM + lane]);
            float w3 = __ldg(&h[(size_t)s3 * DIM + lane + 32]);
            a0 += v0 + v1; b0 += v2 + v3;
            a1 += w0 + w1; b1 += w2 + w3;
        }
        for (; jj < cnt; ++jj) {
            int s = __shfl_sync(0xffffffffu, idx, jj);
            a0 += __ldg(&h[(size_t)s * DIM + lane]);
            a1 += __ldg(&h[(size_t)s * DIM + lane + 32]);
        }
        j += cnt;
    }
    a0 += b0; a1 += b1;
    float inv = 1.f / fmaxf((float)deg, 1.f);
    const float* hn = h + (size_t)node * DIM;
    g_x[(size_t)node * DIM + lane]      = fmaf(a0, inv, hn[lane]);
    g_x[(size_t)node * DIM + lane + 32] = fmaf(a1, inv, hn[lane + 32]);
}

// ---------------- fused MLP: out = relu(relu(x@W1+b1)@W2+b2), + BN partials ----
// block 256 thr, M_TILE=128 nodes, 1 CTA/SM (193KB smem).
// hidden processed in 4 chunks of 64 cols through transposed smem buffer sHT.
#define SM_W1   0                       // [64][256]            16384 f
#define SM_W2   (64*256)                // [256][64]            16384 f
#define SM_AT   (SM_W2 + 256*64)        // [64][130] A^T        8320 f
#define SM_HT   (SM_AT + 64*130)        // [64][130] H^T chunk  8320 f
#define SM_B1   (SM_HT + 64*130)        // [256]
#define SM_B2   (SM_B1 + 256)           // [64]
#define SMEM_MLP_FLOATS (SM_B2 + 64)

__global__ void __launch_bounds__(256)
k_mlp(const float* __restrict__ W1, const float* __restrict__ b1,
      const float* __restrict__ W2, const float* __restrict__ b2,
      float* __restrict__ out) {
    extern __shared__ float sm[];
    float* sW1 = sm + SM_W1;
    float* sW2 = sm + SM_W2;
    float* sAT = sm + SM_AT;
    float* sHT = sm + SM_HT;
    float* sB1 = sm + SM_B1;
    float* sB2 = sm + SM_B2;
    const int t  = threadIdx.x;
    const int m0 = blockIdx.x * 128;

    // ---- stage weights, biases, A^T ----
    {
        float4* d1 = (float4*)sW1;
        const float4* s1 = (const float4*)W1;
        #pragma unroll
        for (int i = t; i < 64 * 256 / 4; i += 256) d1[i] = s1[i];
        float4* d2 = (float4*)sW2;
        const float4* s2 = (const float4*)W2;
        #pragma unroll
        for (int i = t; i < 256 * 64 / 4; i += 256) d2[i] = s2[i];
        if (t < 256) sB1[t] = b1[t];
        if (t < 64)  sB2[t] = b2[t];
        for (int i = t; i < 128 * 16; i += 256) {
            int m = i >> 4, c4 = i & 15;
            float4 v = *(const float4*)&g_x[(size_t)(m0 + m) * DIM + c4 * 4];
            sAT[(c4 * 4 + 0) * 130 + m] = v.x;
            sAT[(c4 * 4 + 1) * 130 + m] = v.y;
            sAT[(c4 * 4 + 2) * 130 + m] = v.z;
            sAT[(c4 * 4 + 3) * 130 + m] = v.w;
        }
    }
    __syncthreads();

    const int pm   = t & 127;        // phase-1: node
    const int half = t >> 7;         // phase-1: which 32-col half of the chunk
    const int tx = t & 15, ty = t >> 4;   // phase-2 mapping

    unsigned long long acc[4][4];    // phase-2 out acc: [node-pair][col]
    #pragma unroll
    for (int p = 0; p < 4; ++p)
        #pragma unroll
        for (int j = 0; j < 4; ++j) acc[p][j] = 0ull;

    for (int cc = 0; cc < 4; ++cc) {
        // ---- phase 1: H^T chunk = relu(A @ W1[:, cc*64 : cc*64+64] + b1)
        unsigned long long hacc[16];
        #pragma unroll
        for (int j = 0; j < 16; ++j) hacc[j] = 0ull;
        #pragma unroll 4
        for (int k = 0; k < 64; ++k) {
            float a = sAT[k * 130 + pm];
            unsigned long long a2 = pack2(a, a);
            const unsigned long long* wrow =
                (const unsigned long long*)&sW1[k * 256 + cc * 64 + half * 32];
            #pragma unroll
            for (int j = 0; j < 16; ++j) fma2(hacc[j], a2, wrow[j]);
        }
        __syncthreads();   // phase-2 of previous chunk done reading sHT
        #pragma unroll
        for (int j = 0; j < 16; ++j) {
            int cl = half * 32 + 2 * j;          // col within chunk
            int c  = cc * 64 + cl;
            float lo, hi;
            unpack2(hacc[j], lo, hi);
            lo = fmaxf(lo + sB1[c], 0.f);
            hi = fmaxf(hi + sB1[c + 1], 0.f);
            sHT[(cl + 0) * 130 + pm] = lo;
            sHT[(cl + 1) * 130 + pm] = hi;
        }
        __syncthreads();

        // ---- phase 2: acc += H_chunk @ W2[cc*64 : cc*64+64, :]
        #pragma unroll 4
        for (int k = 0; k < 64; ++k) {
            unsigned long long apair[4];
            #pragma unroll
            for (int p = 0; p < 4; ++p)
                apair[p] = *(const unsigned long long*)&sHT[k * 130 + ty * 8 + 2 * p];
            #pragma unroll
            for (int j = 0; j < 4; ++j) {
                float b = sW2[(cc * 64 + k) * 64 + tx + 16 * j];
                unsigned long long b2p = pack2(b, b);
                #pragma unroll
                for (int p = 0; p < 4; ++p) fma2(acc[p][j], apair[p], b2p);
            }
        }
    }
    __syncthreads();   // done with sHT; reuse for BN reduction

    // ---- epilogue: bias + relu + store + BN partial sums ----
    float csum[4] = {0.f, 0.f, 0.f, 0.f};
    float csq [4] = {0.f, 0.f, 0.f, 0.f};
    #pragma unroll
    for (int p = 0; p < 4; ++p) {
        int mA = m0 + ty * 8 + 2 * p;
        int mB = mA + 1;
        #pragma unroll
        for (int j = 0; j < 4; ++j) {
            int c = tx + 16 * j;
            float lo, hi;
            unpack2(acc[p][j], lo, hi);
            float bv = sB2[c];
            lo = fmaxf(lo + bv, 0.f);
            hi = fmaxf(hi + bv, 0.f);
            if (mA < N_NODES) {
                out[(size_t)mA * DIM + c] = lo;
                csum[j] += lo; csq[j] += lo * lo;
            }
            if (mB < N_NODES) {
                out[(size_t)mB * DIM + c] = hi;
                csum[j] += hi; csq[j] += hi * hi;
            }
        }
    }
    #pragma unroll
    for (int j = 0; j < 4; ++j) {
        int c = tx + 16 * j;
        sHT[c * 16 + ty]        = csum[j];
        sHT[1024 + c * 16 + ty] = csq[j];
    }
    __syncthreads();
    if (t < DIM) {
        float s = 0.f, q = 0.f;
        #pragma unroll
        for (int u = 0; u < 16; ++u) {
            s += sHT[t * 16 + u];
            q += sHT[1024 + t * 16 + u];
        }
        atomicAdd(&g_colsum[t], s);
        atomicAdd(&g_colsq[t],  q);
    }
}

// ---------------- batchnorm ----------------
__global__ void k_bnstats(const float* __restrict__ gamma, const float* __restrict__ beta) {
    int t = threadIdx.x;
    const float invN = 1.f / (float)N_NODES;
    float mean = g_colsum[t] * invN;
    float var  = g_colsq[t] * invN - mean * mean;
    float sc   = gamma[t] * rsqrtf(var + BN_EPS);
    g_scale[t] = sc;
    g_shift[t] = fmaf(-mean, sc, beta[t]);
}

__global__ void k_bnapply(float* __restrict__ out) {
    int i = blockIdx.x * blockDim.x + threadIdx.x;   // float4 index
    if (i < N_NODES * (DIM / 4)) {
        int c4 = i & 15;
        float4 v  = ((float4*)out)[i];
        float4 sc = ((const float4*)g_scale)[c4];
        float4 sh = ((const float4*)g_shift)[c4];
        v.x = fmaf(v.x, sc.x, sh.x);
        v.y = fmaf(v.y, sc.y, sh.y);
        v.z = fmaf(v.z, sc.z, sh.z);
        v.w = fmaf(v.w, sc.w, sh.w);
        ((float4*)out)[i] = v;
    }
}

// ---------------- launch ----------------
extern "C" void kernel_launch(void* const* d_in, const int* in_sizes, int n_in,
                              void* d_out, int out_size) {
    const float* h     = (const float*)d_in[0];
    const float* W1    = (const float*)d_in[1];
    const float* b1    = (const float*)d_in[2];
    const float* W2    = (const float*)d_in[3];
    const float* b2    = (const float*)d_in[4];
    const float* gamma = (const float*)d_in[5];
    const float* beta  = (const float*)d_in[6];
    const int*   src   = (const int*)d_in[7];
    const int*   dst   = (const int*)d_in[8];
    const int    E     = in_sizes[7];
    float* out = (float*)d_out;

    cudaFuncSetAttribute(k_mlp, cudaFuncAttributeMaxDynamicSharedMemorySize,
                         SMEM_MLP_FLOATS * (int)sizeof(float));

    const int eb = (E + 255) / 256;
    k_zero<<<(N_PAD + 255) / 256, 256>>>();
    k_hist<<<eb, 256>>>(dst, E);
    k_scan<<<(N_NODES + 255) / 256, 256>>>();
    k_fill<<<eb, 256>>>(src, dst, E);
    k_agg<<<(N_NODES * 32 + 255) / 256, 256>>>(h);
    k_mlp<<<(N_NODES + 127) / 128, 256, SMEM_MLP_FLOATS * sizeof(float)>>>(W1, b1, W2, b2, out);
    k_bnstats<<<1, DIM>>>(gamma, beta);
    k_bnapply<<<(N_NODES * (DIM / 4) + 255) / 256, 256>>>(out);
}